// round 5
// baseline (speedup 1.0000x reference)
#include <cuda_runtime.h>
#include <cuda_bf16.h>
#include <cstdint>

#define B 384
#define D 128
#define TS 32                  // Gram tile size
#define GT (B / TS)            // 12 tiles per dim
#define NBLK (GT * GT)         // 144 blocks (single wave, all resident)
#define THREADS 256
#define PITCH4 33              // float4 pitch for 32-float4 rows (+1 pad)
#define MARGIN 0.5f

__device__ float g_G[B * B];         // Gram matrix scratch (590KB)
__device__ float g_psum[NBLK];
__device__ float g_pcnt[NBLK];
__device__ unsigned int g_done;      // phase-1 completion counter (zero-init)
__device__ unsigned int g_ticket;    // phase-2 completion ticket (zero-init)

__device__ __forceinline__ void cp_async16(uint32_t dst, const void* src) {
    asm volatile("cp.async.cg.shared.global [%0], [%1], 16;" :: "r"(dst), "l"(src));
}

__global__ __launch_bounds__(THREADS) void triplet_kernel(
    const float* __restrict__ emb,
    const int* __restrict__ labels,
    float* __restrict__ out)
{
    __shared__ float4 sA[TS * PITCH4];
    __shared__ float4 sB[TS * PITCH4];
    __shared__ float  sdiag[B];
    __shared__ int    slab[B];
    __shared__ float  dpos[B];
    __shared__ int    npos;
    __shared__ float  rsum[THREADS / 32];
    __shared__ float  rcnt[THREADS / 32];
    __shared__ int    is_last;

    const int tid = threadIdx.x;
    const int bid = blockIdx.x;
    const int ty  = bid / GT;
    const int tx  = bid % GT;

    // ================= PHASE 1: Gram tile G[32ty.., 32tx..] =================
    const float4* g4 = (const float4*)emb;          // B x 32 float4
    const uint32_t sA_u = (uint32_t)__cvta_generic_to_shared(sA);
    const uint32_t sB_u = (uint32_t)__cvta_generic_to_shared(sB);

    #pragma unroll
    for (int it = 0; it < (TS * (D / 4)) / THREADS; it++) {   // 4 iters
        int g = tid + THREADS * it;                  // 0..1023
        int r = g >> 5, c = g & 31;
        uint32_t soff = (uint32_t)((r * PITCH4 + c) * 16);
        cp_async16(sA_u + soff, g4 + (ty * TS + r) * (D / 4) + c);
        cp_async16(sB_u + soff, g4 + (tx * TS + r) * (D / 4) + c);
    }
    asm volatile("cp.async.commit_group;" ::: "memory");

    // overlap: stage labels while tiles land
    if (tid < B - THREADS) slab[THREADS + tid] = labels[THREADS + tid];
    slab[tid] = labels[tid];

    asm volatile("cp.async.wait_group 0;" ::: "memory");
    __syncthreads();

    const int i  = tid & 31;          // output row within tile
    const int jg = tid >> 5;          // output col group (4 cols)
    float acc0 = 0.f, acc1 = 0.f, acc2 = 0.f, acc3 = 0.f;
    const float4* arow = sA + i * PITCH4;
    const float4* b0 = sB + (jg * 4 + 0) * PITCH4;
    const float4* b1 = sB + (jg * 4 + 1) * PITCH4;
    const float4* b2 = sB + (jg * 4 + 2) * PITCH4;
    const float4* b3 = sB + (jg * 4 + 3) * PITCH4;

    #pragma unroll 8
    for (int k = 0; k < D / 4; k++) {
        float4 x = arow[k];
        float4 p = b0[k];   // warp-uniform -> smem broadcast
        acc0 = fmaf(x.x, p.x, fmaf(x.y, p.y, fmaf(x.z, p.z, fmaf(x.w, p.w, acc0))));
        p = b1[k];
        acc1 = fmaf(x.x, p.x, fmaf(x.y, p.y, fmaf(x.z, p.z, fmaf(x.w, p.w, acc1))));
        p = b2[k];
        acc2 = fmaf(x.x, p.x, fmaf(x.y, p.y, fmaf(x.z, p.z, fmaf(x.w, p.w, acc2))));
        p = b3[k];
        acc3 = fmaf(x.x, p.x, fmaf(x.y, p.y, fmaf(x.z, p.z, fmaf(x.w, p.w, acc3))));
    }

    {
        float4 o = make_float4(acc0, acc1, acc2, acc3);
        *(float4*)&g_G[(ty * TS + i) * B + tx * TS + jg * 4] = o;
    }

    // ================= GRID-WIDE SYNC =================
    __threadfence();                  // each thread publishes its own G stores
    __syncthreads();
    if (tid == 0) {
        atomicAdd(&g_done, 1u);
        volatile unsigned int* vd = &g_done;
        while (*vd < NBLK) { }
    }
    __syncthreads();
    __threadfence();                  // acquire: G now globally valid

    // ================= PHASE 2: triplet sums from G =================
    for (int j = tid; j < B; j += THREADS)
        sdiag[j] = __ldcg(&g_G[j * (B + 1)]);
    __syncthreads();

    float bsum = 0.f, bcnt = 0.f;

    for (int a = bid; a < B; a += NBLK) {           // <=3 anchors per block
        const float Gaa = sdiag[a];
        const int   la  = slab[a];

        if (tid == 0) npos = 0;
        __syncthreads();

        float dj[2];
        #pragma unroll
        for (int u = 0; u < 2; u++) {
            int j = tid + THREADS * u;
            if (j < B) {
                float Gaj = __ldcg(&g_G[a * B + j]);
                dj[u] = fmaxf(Gaa - 2.f * Gaj + sdiag[j], 0.f);
                if (slab[j] == la && j != a) {
                    int idx = atomicAdd(&npos, 1);
                    dpos[idx] = dj[u];
                }
            }
        }
        __syncthreads();

        const int np = npos;
        #pragma unroll
        for (int u = 0; u < 2; u++) {
            int j = tid + THREADS * u;
            if (j < B && slab[j] != la) {
                const float dn = dj[u];
                for (int p = 0; p < np; p++) {
                    float v = dpos[p] - dn + MARGIN;
                    if (v > 1e-16f) { bsum += v; bcnt += 1.f; }
                }
            }
        }
        __syncthreads();
    }

    // ---- block reduction (8 warps) ----
    const int lane = tid & 31;
    const int warp = tid >> 5;
    #pragma unroll
    for (int off = 16; off > 0; off >>= 1) {
        bsum += __shfl_down_sync(0xFFFFFFFFu, bsum, off);
        bcnt += __shfl_down_sync(0xFFFFFFFFu, bcnt, off);
    }
    if (lane == 0) { rsum[warp] = bsum; rcnt[warp] = bcnt; }
    __syncthreads();
    if (warp == 0) {
        float s = (lane < THREADS / 32) ? rsum[lane] : 0.f;
        float c = (lane < THREADS / 32) ? rcnt[lane] : 0.f;
        #pragma unroll
        for (int off = 16; off > 0; off >>= 1) {
            s += __shfl_down_sync(0xFFFFFFFFu, s, off);
            c += __shfl_down_sync(0xFFFFFFFFu, c, off);
        }
        if (lane == 0) {
            g_psum[bid] = s;
            g_pcnt[bid] = c;
        }
    }

    // ---- last-block final reduction + counter reset for graph replay ----
    __threadfence();
    if (tid == 0) {
        unsigned int tk = atomicAdd(&g_ticket, 1u);
        is_last = (tk == NBLK - 1);
    }
    __syncthreads();

    if (is_last && warp == 0) {
        __threadfence();
        volatile float* vs = g_psum;
        volatile float* vc = g_pcnt;
        double s = 0.0, c = 0.0;
        #pragma unroll
        for (int idx = lane; idx < NBLK; idx += 32) {
            s += (double)vs[idx];
            c += (double)vc[idx];
        }
        #pragma unroll
        for (int off = 16; off > 0; off >>= 1) {
            s += __shfl_down_sync(0xFFFFFFFFu, s, off);
            c += __shfl_down_sync(0xFFFFFFFFu, c, off);
        }
        if (lane == 0) {
            out[0] = (float)(s / (c + 1e-16));
            g_ticket = 0;                 // reset for next graph replay
            g_done   = 0;
        }
    }
}

extern "C" void kernel_launch(void* const* d_in, const int* in_sizes, int n_in,
                              void* d_out, int out_size) {
    const float* emb    = (const float*)d_in[0];
    const int*   labels = (const int*)d_in[1];
    float*       out    = (float*)d_out;

    triplet_kernel<<<NBLK, THREADS>>>(emb, labels, out);
}

// round 6
// speedup vs baseline: 1.1425x; 1.1425x over previous
#include <cuda_runtime.h>
#include <cuda_bf16.h>
#include <cstdint>

#define B 384
#define D 128
#define NA 3                   // anchors per block
#define NB (B / NA)            // 128 blocks -> single wave
#define THREADS 768            // 24 warps: split-K by 2
#define ROWF4 33               // padded row pitch in float4 (528B)
#define MARGIN 0.5f
#define NWARP (THREADS / 32)   // 24

__device__ float g_psum[NB];
__device__ float g_pcnt[NB];
__device__ unsigned int g_ticket;   // zero-init; reset by last block

__device__ __forceinline__ void cp_async16(uint32_t dst, const void* src) {
    asm volatile("cp.async.cg.shared.global [%0], [%1], 16;" :: "r"(dst), "l"(src));
}

__global__ __launch_bounds__(THREADS, 1) void triplet_kernel(
    const float* __restrict__ emb,
    const int* __restrict__ labels,
    float* __restrict__ out)
{
    extern __shared__ float4 semb[];        // [B][ROWF4] staged embeddings
    __shared__ float4 part[B];              // upper-half partials {dot0,dot1,dot2,sq}
    __shared__ int    slab[B];
    __shared__ float  dpos[NA][B];
    __shared__ int    npos[NA];
    __shared__ float  sqa_s[NA];
    __shared__ float  rsum[NWARP];
    __shared__ float  rcnt[NWARP];
    __shared__ int    is_last;

    const int t  = threadIdx.x;
    const int ab = blockIdx.x * NA;
    const float4* g4 = (const float4*)emb;  // B*32 float4

    // ---- stage whole matrix, coalesced cp.async (16 float4 per thread) ----
    const uint32_t semb_u = (uint32_t)__cvta_generic_to_shared(semb);
    #pragma unroll
    for (int i = 0; i < (B * D / 4) / THREADS; i++) {   // 16 iters
        int g = t + THREADS * i;
        uint32_t dst = semb_u + (uint32_t)(((g >> 5) * ROWF4 + (g & 31)) * 16);
        cp_async16(dst, g4 + g);
    }
    asm volatile("cp.async.commit_group;" ::: "memory");

    if (t < B) slab[t] = labels[t];
    if (t < NA) npos[t] = 0;

    asm volatile("cp.async.wait_group 0;" ::: "memory");
    __syncthreads();

    // ---- split-K dot products: lower half k[0,16), upper half k[16,32) ----
    const int  row = (t < B) ? t : (t - B);
    const int  kofs = (t < B) ? 0 : (D / 8);        // in float4 units (16)
    const float4* xrow = semb + row * ROWF4 + kofs;
    const float4* arow = semb + ab * ROWF4 + kofs;

    float dot[NA] = {0.f, 0.f, 0.f};
    float sq = 0.f;
    #pragma unroll
    for (int k = 0; k < D / 8; k++) {               // 16 iters
        float4 x = xrow[k];
        sq = fmaf(x.x, x.x, fmaf(x.y, x.y, fmaf(x.z, x.z, fmaf(x.w, x.w, sq))));
        #pragma unroll
        for (int aa = 0; aa < NA; aa++) {
            float4 e = arow[aa * ROWF4 + k];        // warp-uniform -> broadcast
            dot[aa] = fmaf(x.x, e.x, fmaf(x.y, e.y,
                      fmaf(x.z, e.z, fmaf(x.w, e.w, dot[aa]))));
        }
    }

    if (t >= B) part[row] = make_float4(dot[0], dot[1], dot[2], sq);
    __syncthreads();

    float sum = 0.f, cnt = 0.f;
    float dist[NA];
    int lt = 0;

    if (t < B) {
        float4 p = part[row];
        dot[0] += p.x; dot[1] += p.y; dot[2] += p.z; sq += p.w;

        if (t >= ab && t < ab + NA) sqa_s[t - ab] = sq;
    }
    __syncthreads();

    if (t < B) {
        lt = slab[t];
        #pragma unroll
        for (int aa = 0; aa < NA; aa++) {
            dist[aa] = fmaxf(sqa_s[aa] - 2.f * dot[aa] + sq, 0.f);
            if (lt == slab[ab + aa] && t != ab + aa) {
                int idx = atomicAdd(&npos[aa], 1);
                dpos[aa][idx] = dist[aa];
            }
        }
    }
    __syncthreads();

    if (t < B) {
        #pragma unroll
        for (int aa = 0; aa < NA; aa++) {
            if (lt != slab[ab + aa]) {
                const float dn = dist[aa];
                const int np = npos[aa];
                for (int p = 0; p < np; p++) {
                    float v = dpos[aa][p] - dn + MARGIN;
                    if (v > 1e-16f) { sum += v; cnt += 1.f; }
                }
            }
        }
    }

    // ---- block reduction over 24 warps (upper warps contribute 0) ----
    const int lane = t & 31;
    const int warp = t >> 5;
    #pragma unroll
    for (int off = 16; off > 0; off >>= 1) {
        sum += __shfl_down_sync(0xFFFFFFFFu, sum, off);
        cnt += __shfl_down_sync(0xFFFFFFFFu, cnt, off);
    }
    if (lane == 0) { rsum[warp] = sum; rcnt[warp] = cnt; }
    __syncthreads();
    if (warp == 0) {
        float s = (lane < NWARP) ? rsum[lane] : 0.f;
        float c = (lane < NWARP) ? rcnt[lane] : 0.f;
        #pragma unroll
        for (int off = 16; off > 0; off >>= 1) {
            s += __shfl_down_sync(0xFFFFFFFFu, s, off);
            c += __shfl_down_sync(0xFFFFFFFFu, c, off);
        }
        if (lane == 0) {
            g_psum[blockIdx.x] = s;
            g_pcnt[blockIdx.x] = c;
        }
    }

    // ---- last-block final reduction ----
    __threadfence();
    if (t == 0) {
        unsigned int tk = atomicAdd(&g_ticket, 1u);
        is_last = (tk == NB - 1);
    }
    __syncthreads();

    if (is_last && warp == 0) {
        __threadfence();
        volatile float* vs = g_psum;
        volatile float* vc = g_pcnt;
        double s = 0.0, c = 0.0;
        #pragma unroll
        for (int i = lane; i < NB; i += 32) {
            s += (double)vs[i];
            c += (double)vc[i];
        }
        #pragma unroll
        for (int off = 16; off > 0; off >>= 1) {
            s += __shfl_down_sync(0xFFFFFFFFu, s, off);
            c += __shfl_down_sync(0xFFFFFFFFu, c, off);
        }
        if (lane == 0) {
            out[0] = (float)(s / (c + 1e-16));
            g_ticket = 0;                       // reset for graph replay
        }
    }
}

extern "C" void kernel_launch(void* const* d_in, const int* in_sizes, int n_in,
                              void* d_out, int out_size) {
    const float* emb    = (const float*)d_in[0];
    const int*   labels = (const int*)d_in[1];
    float*       out    = (float*)d_out;

    const size_t smem = (size_t)B * ROWF4 * sizeof(float4);   // 202,752 B dynamic
    cudaFuncSetAttribute(triplet_kernel,
                         cudaFuncAttributeMaxDynamicSharedMemorySize, (int)smem);

    triplet_kernel<<<NB, THREADS, smem>>>(emb, labels, out);
}

// round 8
// speedup vs baseline: 1.2922x; 1.1310x over previous
#include <cuda_runtime.h>
#include <cuda_bf16.h>
#include <cstdint>

#define B 384
#define D 128
#define TS 32                   // Gram tile size
#define GT (B / TS)             // 12 tiles per dim
#define NBLK1 (GT * GT)         // 144 gram blocks
#define THR1 256
#define PITCH4 33               // float4 pitch (+1 pad) -> conflict-free
#define NA 3
#define NB (B / NA)             // 128 triplet blocks
#define THR2 384
#define NWARP2 (THR2 / 32)      // 12
#define MARGIN 0.5f

__device__ float g_G[B * B];          // Gram matrix scratch
__device__ float g_nrm[B];            // squared norms
__device__ float g_psum[NB];
__device__ float g_pcnt[NB];
__device__ unsigned int g_ticket;     // zero-init; reset by last block

__device__ __forceinline__ void cp_async16(uint32_t dst, const void* src) {
    asm volatile("cp.async.cg.shared.global [%0], [%1], 16;" :: "r"(dst), "l"(src));
}

// ======================= Kernel 1: G = E * E^T (tiled) =======================
__global__ __launch_bounds__(THR1) void gram_kernel(const float* __restrict__ emb)
{
    __shared__ float4 sA[TS * PITCH4];
    __shared__ float4 sB[TS * PITCH4];

    const int tid = threadIdx.x;
    const int ty  = blockIdx.x / GT;
    const int tx  = blockIdx.x % GT;

    const float4* g4 = (const float4*)emb;         // B x 32 float4
    const uint32_t sA_u = (uint32_t)__cvta_generic_to_shared(sA);
    const uint32_t sB_u = (uint32_t)__cvta_generic_to_shared(sB);

    #pragma unroll
    for (int it = 0; it < (TS * (D / 4)) / THR1; it++) {    // 4 iters
        int g = tid + THR1 * it;                    // 0..1023
        int r = g >> 5, c = g & 31;
        uint32_t soff = (uint32_t)((r * PITCH4 + c) * 16);
        cp_async16(sA_u + soff, g4 + (ty * TS + r) * (D / 4) + c);
        cp_async16(sB_u + soff, g4 + (tx * TS + r) * (D / 4) + c);
    }
    asm volatile("cp.async.commit_group;" ::: "memory");
    asm volatile("cp.async.wait_group 0;" ::: "memory");
    __syncthreads();

    // diagonal blocks also produce the norm vector (deterministic shfl tree)
    if (ty == tx) {
        const int r = tid >> 3;        // 0..31
        const int q = tid & 7;         // 8-lane groups
        const float4* row = sA + r * PITCH4;
        float p = 0.f;
        #pragma unroll
        for (int c = 0; c < 4; c++) {
            float4 x = row[q * 4 + c];
            p = fmaf(x.x, x.x, fmaf(x.y, x.y, fmaf(x.z, x.z, fmaf(x.w, x.w, p))));
        }
        p += __shfl_down_sync(0xFFFFFFFFu, p, 4, 8);
        p += __shfl_down_sync(0xFFFFFFFFu, p, 2, 8);
        p += __shfl_down_sync(0xFFFFFFFFu, p, 1, 8);
        if (q == 0) g_nrm[ty * TS + r] = p;
    }

    // 32x32 output tile: thread -> row i, 4 cols at jg*4
    const int i  = tid & 31;
    const int jg = tid >> 5;
    float a0 = 0.f, a1 = 0.f, a2 = 0.f, a3 = 0.f;
    const float4* arow = sA + i * PITCH4;
    const float4* b0 = sB + (jg * 4 + 0) * PITCH4;
    const float4* b1 = sB + (jg * 4 + 1) * PITCH4;
    const float4* b2 = sB + (jg * 4 + 2) * PITCH4;
    const float4* b3 = sB + (jg * 4 + 3) * PITCH4;

    #pragma unroll 8
    for (int k = 0; k < D / 4; k++) {
        float4 x = arow[k];
        float4 p = b0[k];   // warp-uniform -> broadcast
        a0 = fmaf(x.x, p.x, fmaf(x.y, p.y, fmaf(x.z, p.z, fmaf(x.w, p.w, a0))));
        p = b1[k];
        a1 = fmaf(x.x, p.x, fmaf(x.y, p.y, fmaf(x.z, p.z, fmaf(x.w, p.w, a1))));
        p = b2[k];
        a2 = fmaf(x.x, p.x, fmaf(x.y, p.y, fmaf(x.z, p.z, fmaf(x.w, p.w, a2))));
        p = b3[k];
        a3 = fmaf(x.x, p.x, fmaf(x.y, p.y, fmaf(x.z, p.z, fmaf(x.w, p.w, a3))));
    }

    *(float4*)&g_G[(ty * TS + i) * B + tx * TS + jg * 4] = make_float4(a0, a1, a2, a3);
}

// ================= Kernel 2: triplet reduction from G ========================
__global__ __launch_bounds__(THR2) void triplet_kernel(
    const int* __restrict__ labels,
    float* __restrict__ out)
{
    __shared__ float snrm[B];
    __shared__ int   slab[B];
    __shared__ float dpos[NA][B];
    __shared__ int   npos[NA];
    __shared__ float rsum[NWARP2];
    __shared__ float rcnt[NWARP2];
    __shared__ int   is_last;

    const int t  = threadIdx.x;      // == column j
    const int ab = blockIdx.x * NA;

    snrm[t] = g_nrm[t];
    slab[t] = labels[t];
    if (t < NA) npos[t] = 0;
    __syncthreads();

    const int lt = slab[t];
    float dist[NA];
    #pragma unroll
    for (int aa = 0; aa < NA; aa++) {
        const int a = ab + aa;
        float Gaj = __ldcg(&g_G[a * B + t]);          // coalesced row read
        dist[aa] = fmaxf(snrm[a] - 2.f * Gaj + snrm[t], 0.f);
        if (lt == slab[a] && t != a) {
            int idx = atomicAdd(&npos[aa], 1);
            dpos[aa][idx] = dist[aa];
        }
    }
    __syncthreads();

    float sum = 0.f, cnt = 0.f;
    #pragma unroll
    for (int aa = 0; aa < NA; aa++) {
        if (lt != slab[ab + aa]) {
            const float dn = dist[aa];
            const int np = npos[aa];
            for (int p = 0; p < np; p++) {
                float v = dpos[aa][p] - dn + MARGIN;
                if (v > 1e-16f) { sum += v; cnt += 1.f; }
            }
        }
    }

    // block reduction (12 warps)
    const int lane = t & 31;
    const int warp = t >> 5;
    #pragma unroll
    for (int off = 16; off > 0; off >>= 1) {
        sum += __shfl_down_sync(0xFFFFFFFFu, sum, off);
        cnt += __shfl_down_sync(0xFFFFFFFFu, cnt, off);
    }
    if (lane == 0) { rsum[warp] = sum; rcnt[warp] = cnt; }
    __syncthreads();
    if (warp == 0) {
        float s = (lane < NWARP2) ? rsum[lane] : 0.f;
        float c = (lane < NWARP2) ? rcnt[lane] : 0.f;
        #pragma unroll
        for (int off = 16; off > 0; off >>= 1) {
            s += __shfl_down_sync(0xFFFFFFFFu, s, off);
            c += __shfl_down_sync(0xFFFFFFFFu, c, off);
        }
        if (lane == 0) {
            g_psum[blockIdx.x] = s;
            g_pcnt[blockIdx.x] = c;
        }
    }

    // last-block final reduction
    __threadfence();
    if (t == 0) {
        unsigned int tk = atomicAdd(&g_ticket, 1u);
        is_last = (tk == NB - 1);
    }
    __syncthreads();

    if (is_last && warp == 0) {
        __threadfence();
        volatile float* vs = g_psum;
        volatile float* vc = g_pcnt;
        double s = 0.0, c = 0.0;
        #pragma unroll
        for (int i = lane; i < NB; i += 32) {
            s += (double)vs[i];
            c += (double)vc[i];
        }
        #pragma unroll
        for (int off = 16; off > 0; off >>= 1) {
            s += __shfl_down_sync(0xFFFFFFFFu, s, off);
            c += __shfl_down_sync(0xFFFFFFFFu, c, off);
        }
        if (lane == 0) {
            out[0] = (float)(s / (c + 1e-16));
            g_ticket = 0;                  // reset for graph replay
        }
    }
}

extern "C" void kernel_launch(void* const* d_in, const int* in_sizes, int n_in,
                              void* d_out, int out_size) {
    const float* emb    = (const float*)d_in[0];
    const int*   labels = (const int*)d_in[1];
    float*       out    = (float*)d_out;

    gram_kernel<<<NBLK1, THR1>>>(emb);
    triplet_kernel<<<NB, THR2>>>(labels, out);
}